// round 7
// baseline (speedup 1.0000x reference)
#include <cuda_runtime.h>
#include <math.h>

// Problem constants
#define BB 256
#define DD 128
#define TT 512
#define HH 512

// Decomposition: 4 groups x 32 CTAs. Group g owns batches [64g, 64g+64).
// CTA c in a group owns h-columns [16c,16c+16) and z-columns [4c,4c+4).
#define NGROUP 4
#define CPG 32
#define MB 64                   // batches per group
#define NCTA (NGROUP * CPG)
#define NTHREADS 256
#define WS_STRIDE 49            // 48 weight rows + 1 pad (conflict-free k-major)
#define WF_STRIDE 5             // 4 fc rows + 1 pad
#define KT 128                  // k-tile staged in smem

// smem layout (floats): Ws[512*49] | Wi[128*49] | Wf[512*5] | hs[128*64]
#define SM_WS   0
#define SM_WI   (512 * WS_STRIDE)
#define SM_WF   (SM_WI + 128 * WS_STRIDE)
#define SM_HS   (SM_WF + 512 * WF_STRIDE)
#define SM_FLOATS (SM_HS + KT * MB)
#define SMEM_BYTES (SM_FLOATS * 4)

// Global state (allowed: __device__ arrays). Zero-initialized at module load.
__device__ __align__(16) float g_hbuf[NGROUP * HH * MB];  // [g][k][b] k-major
__device__ __align__(16) float g_zbuf[NGROUP * DD * MB];  // [g][col][b]
__device__ unsigned g_cnt[NGROUP];
__device__ volatile unsigned g_gen[NGROUP];

// Sense-reversing group barrier (32 co-resident CTAs). next_gen is tracked
// uniformly in registers; the generation counter persists across graph replays
// (we snapshot it at kernel start, so behavior is identical every replay).
__device__ __forceinline__ void group_barrier(int g, unsigned &next_gen) {
    __syncthreads();
    if (threadIdx.x == 0) {
        __threadfence();  // publish this CTA's global writes (gpu scope)
        unsigned prev = atomicAdd(&g_cnt[g], 1u);
        if (prev == CPG - 1) {
            g_cnt[g] = 0;
            __threadfence();
            g_gen[g] = next_gen;      // release (volatile, L1-bypassing)
        } else {
            while ((int)(g_gen[g] - next_gen) < 0) { }
        }
        __threadfence();  // acquire side; on sm_103a also invalidates L1D
    }
    next_gen++;
    __syncthreads();
}

// Stage an 8192-float (KT x MB) tile global->smem, L2-coherent loads.
__device__ __forceinline__ void stage_tile(float *dst, const float *src) {
    const float4 *s4 = (const float4 *)src;
    float4 *d4 = (float4 *)dst;
    const int tid = threadIdx.x;
#pragma unroll
    for (int i = 0; i < (KT * MB / 4) / NTHREADS; ++i)
        d4[tid + i * NTHREADS] = __ldcg(s4 + tid + i * NTHREADS);
}

__global__ __launch_bounds__(NTHREADS, 1)
void gru_decoder_kernel(const float *__restrict__ z_in,
                        const float *__restrict__ W_ih,
                        const float *__restrict__ W_hh,
                        const float *__restrict__ b_ih,
                        const float *__restrict__ b_hh,
                        const float *__restrict__ fc_W,
                        const float *__restrict__ fc_b,
                        float *__restrict__ out) {
    extern __shared__ float sm[];
    float *Ws = sm + SM_WS;
    float *Wi = sm + SM_WI;
    float *Wf = sm + SM_WF;
    float *hs = sm + SM_HS;
    const float4 *hs4 = (const float4 *)hs;

    const int tid = threadIdx.x;
    const int c = blockIdx.x & (CPG - 1);
    const int g = blockIdx.x >> 5;
    const int tx = tid & 15;        // owned j (within 16-slice)      [gates map]
    const int ty = tid >> 4;        // batch quad (4 batches)         [gates map]
    const int b_d = tid & (MB - 1); // delta batch                    [delta map]
    const int cd = tid >> 6;        // delta col (0..3)               [delta map]
    const int jg = 16 * c + tx;     // owned global h index
    const int colg = 4 * c + cd;    // owned global z col
    const int b0 = g * MB;

    // ---- stage weight slices into smem (k-major, padded: conflict-free) ----
    for (int lr = 0; lr < 48; ++lr) {
        const int row = (lr >> 4) * HH + 16 * c + (lr & 15); // [r|z|n] blocks
        const float *src = W_hh + row * HH;
        for (int k = tid; k < HH; k += NTHREADS) Ws[k * WS_STRIDE + lr] = src[k];
    }
    for (int lr = 0; lr < 48; ++lr) {
        const int row = (lr >> 4) * HH + 16 * c + (lr & 15);
        const float *src = W_ih + row * DD;
        for (int k = tid; k < DD; k += NTHREADS) Wi[k * WS_STRIDE + lr] = src[k];
    }
    for (int rr = 0; rr < 4; ++rr) {
        const float *src = fc_W + (4 * c + rr) * HH;
        for (int k = tid; k < HH; k += NTHREADS) Wf[k * WF_STRIDE + rr] = src[k];
    }

    // ---- per-thread constants ----
    const float br_s = b_ih[jg] + b_hh[jg];
    const float bz_s = b_ih[HH + jg] + b_hh[HH + jg];
    const float bin_s = b_ih[2 * HH + jg];
    const float bhn_s = b_hh[2 * HH + jg];
    const float fcb = fc_b[colg];

    // ---- z0 init: write t=0 output, seed zbuf, keep owned z in a register ----
    float z_reg = z_in[(b0 + b_d) * (DD * TT) + colg * TT + 0];
    g_zbuf[(g * DD + colg) * MB + b_d] = z_reg;
    out[(b0 + b_d) * (DD * TT) + colg * TT + 0] = z_reg;

    float hprev[4] = {0.f, 0.f, 0.f, 0.f};

    unsigned next_gen = g_gen[g] + 1;   // snapshot (safe: release needs our arrival)
    group_barrier(g, next_gen);         // zbuf visible to whole group

    const float *hbuf = g_hbuf + g * HH * MB;
    const float *zbuf = g_zbuf + g * DD * MB;

    for (int t = 1; t <= TT; ++t) {
        float accr[4] = {br_s, br_s, br_s, br_s};   // r-gate pre-activation
        float accz[4] = {bz_s, bz_s, bz_s, bz_s};   // z-gate pre-activation
        float accin[4] = {bin_s, bin_s, bin_s, bin_s}; // i_n
        float acchn[4] = {bhn_s, bhn_s, bhn_s, bhn_s}; // h_n
        float dacc = fcb;

        // ---- h-pass: gh_t and delta_{t-1} fused over the same staged h ----
        if (t > 1) {
            for (int k0 = 0; k0 < HH; k0 += KT) {
                __syncthreads();
                stage_tile(hs, hbuf + k0 * MB);
                __syncthreads();

                const float *wrow = Ws + k0 * WS_STRIDE;
                const float *wfp = Wf + k0 * WF_STRIDE;
                const float4 *h4p = hs4 + ty;
                const float *hsp = hs + b_d;
#pragma unroll 4
                for (int kk = 0; kk < KT; ++kk) {
                    const float4 h4 = *h4p;
                    const float wr = wrow[tx];
                    const float wz = wrow[16 + tx];
                    const float wn = wrow[32 + tx];
                    accr[0] += wr * h4.x; accr[1] += wr * h4.y;
                    accr[2] += wr * h4.z; accr[3] += wr * h4.w;
                    accz[0] += wz * h4.x; accz[1] += wz * h4.y;
                    accz[2] += wz * h4.z; accz[3] += wz * h4.w;
                    acchn[0] += wn * h4.x; acchn[1] += wn * h4.y;
                    acchn[2] += wn * h4.z; acchn[3] += wn * h4.w;
                    dacc += wfp[cd] * (*hsp);
                    h4p += MB / 4; hsp += MB;
                    wrow += WS_STRIDE; wfp += WF_STRIDE;
                }
            }
            // z_{t-1} = z_{t-2} + delta_{t-1}; write output slice t-1
            z_reg += dacc;
            g_zbuf[(g * DD + colg) * MB + b_d] = z_reg;
            out[(b0 + b_d) * (DD * TT) + colg * TT + (t - 1)] = z_reg;
        }

        group_barrier(g, next_gen);  // z complete across group

        if (t < TT) {
            // ---- z-pass: gi_t over full z_{t-1} (one KT=128 tile) ----
            stage_tile(hs, zbuf);
            __syncthreads();

            const float *wrow = Wi;
            const float4 *x4p = hs4 + ty;
#pragma unroll 4
            for (int kk = 0; kk < DD; ++kk) {
                const float4 x4 = *x4p;
                const float wr = wrow[tx];
                const float wz = wrow[16 + tx];
                const float wn = wrow[32 + tx];
                accr[0] += wr * x4.x; accr[1] += wr * x4.y;
                accr[2] += wr * x4.z; accr[3] += wr * x4.w;
                accz[0] += wz * x4.x; accz[1] += wz * x4.y;
                accz[2] += wz * x4.z; accz[3] += wz * x4.w;
                accin[0] += wn * x4.x; accin[1] += wn * x4.y;
                accin[2] += wn * x4.z; accin[3] += wn * x4.w;
                x4p += MB / 4; wrow += WS_STRIDE;
            }

            // ---- gates + h update (owned slice stays in registers) ----
#pragma unroll
            for (int i = 0; i < 4; ++i) {
                const float r = 1.0f / (1.0f + expf(-accr[i]));
                const float zg = 1.0f / (1.0f + expf(-accz[i]));
                const float n = tanhf(accin[i] + r * acchn[i]);
                const float h = (1.0f - zg) * n + zg * hprev[i];
                hprev[i] = h;
                g_hbuf[(g * HH + jg) * MB + 4 * ty + i] = h;
            }
        }

        group_barrier(g, next_gen);  // h complete across group
    }
}

extern "C" void kernel_launch(void* const* d_in, const int* in_sizes, int n_in,
                              void* d_out, int out_size) {
    (void)in_sizes; (void)n_in; (void)out_size;
    const float *z    = (const float *)d_in[0];
    // d_in[1] = e  (unused by the reference computation)
    const float *W_ih = (const float *)d_in[2];
    const float *W_hh = (const float *)d_in[3];
    const float *b_ih = (const float *)d_in[4];
    const float *b_hh = (const float *)d_in[5];
    const float *fc_W = (const float *)d_in[6];
    const float *fc_b = (const float *)d_in[7];
    float *out = (float *)d_out;

    cudaFuncSetAttribute(gru_decoder_kernel,
                         cudaFuncAttributeMaxDynamicSharedMemorySize, SMEM_BYTES);
    gru_decoder_kernel<<<NCTA, NTHREADS, SMEM_BYTES>>>(
        z, W_ih, W_hh, b_ih, b_hh, fc_W, fc_b, out);
}